// round 4
// baseline (speedup 1.0000x reference)
#include <cuda_runtime.h>
#include <cstdint>

// Problem constants (fixed by the reference):
//   B=32, C=18, H=W=256, N_BLOCKS=3
//   output = concat(gen_poses [2,B,C,H,W], step_poses [2,B,C,H,W]) as float32
//
// Plane numbering (each plane = one [H,W] = 65536-float slab):
//   plane in [0, 2*B*C)      : gen half.   k = plane/576, rem = plane%576, c = rem%18
//                              coords from pose{k}[sample 0, c]  (batch-replicated)
//   plane in [2*B*C, 4*B*C)  : step half.  q = plane-1152, s = q/576 (0 or 1),
//                              rem = q%576 indexes (b,c) pair directly: coords at p[2*rem]
//
// Each plane holds at most one 1.0 at offset x*256 + y; everything else is 0.

static constexpr int BC      = 32 * 18;   // 576
static constexpr int C_KP    = 18;
static constexpr int HW      = 256 * 256; // 65536 floats per plane
static constexpr int PLANES  = 4 * BC;    // 2304

__global__ __launch_bounds__(256, 8)
void cbmodel_fill_kernel(const float* __restrict__ pose1,
                         const float* __restrict__ pose2,
                         float* __restrict__ out)
{
    const int plane = blockIdx.x;

    // ---- compute this plane's hot index (all threads redundantly; L1 broadcast) ----
    float cx, cy;
    if (plane < 2 * BC) {
        // gen half: sample-0 coords, replicated over batch
        const int k   = plane / BC;            // 0 -> pose1, 1 -> pose2
        const int rem = plane - k * BC;
        const int c   = rem % C_KP;
        const float* P = k ? pose2 : pose1;    // sample 0 => base offset 0
        cx = P[2 * c];
        cy = P[2 * c + 1];
    } else {
        // step half: per-(b,c) coords, pose1 + s*floor((pose2-pose1)/3)
        const int q   = plane - 2 * BC;
        const int s   = q / BC;                // 0 -> one step, 1 -> two steps
        const int rem = q - s * BC;            // rem = b*18 + c, direct coord index
        const float ax = pose1[2 * rem],     ay = pose1[2 * rem + 1];
        const float bx = pose2[2 * rem],     by = pose2[2 * rem + 1];
        const float sx = floorf((bx - ax) / 3.0f);
        const float sy = floorf((by - ay) / 3.0f);
        // sequential accumulation to reproduce the reference's rounding exactly
        cx = ax + sx;  cy = ay + sy;
        if (s == 1) { cx += sx; cy += sy; }
    }

    // jnp.trunc + int32 cast == C trunc-toward-zero cast (inputs bounded, no overflow)
    const int x = (int)cx;
    const int y = (int)cy;
    const bool valid = (x >= 0) & (x <= 255) & (y >= 0) & (y <= 255);
    const int hot = valid ? ((x << 8) | y) : -1;

    // ---- stream zeros: 16384 float4 stores per plane, coalesced ----
    float4* __restrict__ dst = reinterpret_cast<float4*>(out + (size_t)plane * HW);
    const float4 z = make_float4(0.0f, 0.0f, 0.0f, 0.0f);
    #pragma unroll 4
    for (int i = threadIdx.x; i < HW / 4; i += 256) {
        dst[i] = z;
    }

    // ---- order the conflicting write, then set the single 1.0 ----
    __syncthreads();
    if (threadIdx.x == 0 && hot >= 0) {
        out[(size_t)plane * HW + hot] = 1.0f;
    }
}

extern "C" void kernel_launch(void* const* d_in, const int* in_sizes, int n_in,
                              void* d_out, int out_size)
{
    const float* pose1 = (const float*)d_in[0];   // [32,18,2] float32
    const float* pose2 = (const float*)d_in[1];   // [32,18,2] float32
    float* out = (float*)d_out;                   // 4*576*65536 float32

    (void)in_sizes; (void)n_in; (void)out_size;

    cbmodel_fill_kernel<<<PLANES, 256>>>(pose1, pose2, out);
}

// round 5
// speedup vs baseline: 1.0422x; 1.0422x over previous
#include <cuda_runtime.h>
#include <cstdint>

// CBModel: output = concat(gen_poses [2,32,18,256,256], step_poses [2,32,18,256,256]) fp32
//   = 150,994,944 floats = 604 MB, all zeros except <=2304 elements set to 1.0.
//
// Strategy: driver memset node for the 604 MB zero stream (best-tuned write path),
// then a tiny kernel writes the 2304 hot elements (one thread per plane).
//
// Plane numbering (each plane = one [H,W] = 65536-float slab):
//   plane in [0, 1152)    : gen half.   k = plane/576, rem = plane%576, c = rem%18
//                           coords from pose{k}[sample 0, c] (batch-replicated)
//   plane in [1152, 2304) : step half.  q = plane-1152, s = q/576 (0 or 1),
//                           rem = q%576 = b*18+c indexes coords directly

static constexpr int BC     = 32 * 18;    // 576
static constexpr int C_KP   = 18;
static constexpr int HW     = 256 * 256;  // 65536
static constexpr int PLANES = 4 * BC;     // 2304

__global__ __launch_bounds__(256)
void cbmodel_ones_kernel(const float* __restrict__ pose1,
                         const float* __restrict__ pose2,
                         float* __restrict__ out)
{
    const int plane = blockIdx.x * 256 + threadIdx.x;
    if (plane >= PLANES) return;

    float cx, cy;
    if (plane < 2 * BC) {
        // gen half: sample-0 coords, replicated over batch
        const int k   = plane / BC;            // 0 -> pose1, 1 -> pose2
        const int rem = plane - k * BC;
        const int c   = rem % C_KP;
        const float* P = k ? pose2 : pose1;    // sample 0 => base offset 0
        cx = P[2 * c];
        cy = P[2 * c + 1];
    } else {
        // step half: pose1 + s*floor((pose2-pose1)/3), accumulated sequentially
        // to reproduce the reference's float rounding exactly
        const int q   = plane - 2 * BC;
        const int s   = q / BC;                // 0 -> one step, 1 -> two steps
        const int rem = q - s * BC;            // rem = b*18 + c
        const float ax = pose1[2 * rem],  ay = pose1[2 * rem + 1];
        const float bx = pose2[2 * rem],  by = pose2[2 * rem + 1];
        const float sx = floorf((bx - ax) / 3.0f);
        const float sy = floorf((by - ay) / 3.0f);
        cx = ax + sx;  cy = ay + sy;
        if (s == 1) { cx += sx; cy += sy; }
    }

    // jnp.trunc + int32 cast == C trunc-toward-zero cast (inputs bounded)
    const int x = (int)cx;
    const int y = (int)cy;
    if ((x >= 0) & (x <= 255) & (y >= 0) & (y <= 255)) {
        out[(size_t)plane * HW + (x << 8) + y] = 1.0f;
    }
}

extern "C" void kernel_launch(void* const* d_in, const int* in_sizes, int n_in,
                              void* d_out, int out_size)
{
    const float* pose1 = (const float*)d_in[0];   // [32,18,2] float32
    const float* pose2 = (const float*)d_in[1];   // [32,18,2] float32
    float* out = (float*)d_out;

    (void)in_sizes; (void)n_in;

    // Bulk zero: graph-capturable memset node on the capture (legacy) stream.
    cudaMemsetAsync(d_out, 0, (size_t)out_size * sizeof(float), 0);

    // Sparse ones: one thread per plane, ordered after the memset by the stream.
    cbmodel_ones_kernel<<<(PLANES + 255) / 256, 256>>>(pose1, pose2, out);
}

// round 6
// speedup vs baseline: 1.0484x; 1.0060x over previous
#include <cuda_runtime.h>
#include <cstdint>

// CBModel: output = concat(gen_poses [2,32,18,256,256], step_poses [2,32,18,256,256]) fp32
//   = 150,994,944 floats = 604 MB, all zeros except <=2304 elements set to 1.0.
//
// Strategy:
//   1) cudaMemsetAsync zeros the HEAD (2272 planes, 595.6 MB) — the driver memset
//      path runs at ~7.37 TB/s, the chip's store ceiling.
//   2) One fused kernel (a) fills the 32-plane TAIL with zeros and its hot 1.0s
//      (block-local ordering via __syncthreads), and (b) writes the hot 1.0s for
//      all HEAD planes (ordered after the memset by the stream).
//   This overlaps what used to be a serialized 4.5us ones-kernel with tail fill work.

static constexpr int BC      = 32 * 18;    // 576
static constexpr int C_KP    = 18;
static constexpr int HW      = 256 * 256;  // 65536 floats per plane
static constexpr int PLANES  = 4 * BC;     // 2304

static constexpr int TAIL_PLANES      = 32;
static constexpr int HEAD_PLANES      = PLANES - TAIL_PLANES;   // 2272
static constexpr int BLOCKS_PER_PLANE = 4;
static constexpr int QUARTER          = HW / BLOCKS_PER_PLANE;  // 16384 floats
static constexpr int FILL_BLOCKS      = TAIL_PLANES * BLOCKS_PER_PLANE; // 128
static constexpr int ONES_BLOCKS      = (HEAD_PLANES + 255) / 256;      // 9
static constexpr int GRID             = FILL_BLOCKS + ONES_BLOCKS;      // 137

// Hot index for a plane: -1 if out of bounds, else x*256+y.
// Bit-exact to the reference: jnp.trunc+int32 == C trunc cast; floor_divide via
// floorf((b-a)/3); step coords accumulated sequentially (two float roundings).
__device__ __forceinline__ int plane_hot(int plane,
                                         const float* __restrict__ pose1,
                                         const float* __restrict__ pose2)
{
    float cx, cy;
    if (plane < 2 * BC) {
        // gen half: sample-0 coords, replicated over batch
        const int k   = plane / BC;            // 0 -> pose1, 1 -> pose2
        const int rem = plane - k * BC;
        const int c   = rem % C_KP;
        const float* P = k ? pose2 : pose1;
        cx = P[2 * c];
        cy = P[2 * c + 1];
    } else {
        const int q   = plane - 2 * BC;
        const int s   = q / BC;                // 0 -> one step, 1 -> two steps
        const int rem = q - s * BC;            // rem = b*18 + c
        const float ax = pose1[2 * rem],  ay = pose1[2 * rem + 1];
        const float bx = pose2[2 * rem],  by = pose2[2 * rem + 1];
        const float sx = floorf((bx - ax) / 3.0f);
        const float sy = floorf((by - ay) / 3.0f);
        cx = ax + sx;  cy = ay + sy;
        if (s == 1) { cx += sx; cy += sy; }
    }
    const int x = (int)cx;
    const int y = (int)cy;
    const bool valid = (x >= 0) & (x <= 255) & (y >= 0) & (y <= 255);
    return valid ? ((x << 8) | y) : -1;
}

__global__ __launch_bounds__(256)
void cbmodel_fused_tail_kernel(const float* __restrict__ pose1,
                               const float* __restrict__ pose2,
                               float* __restrict__ out)
{
    const int b = blockIdx.x;

    if (b < FILL_BLOCKS) {
        // ---- tail fill: block b covers quarter (b%4) of plane HEAD+(b/4) ----
        const int plane = HEAD_PLANES + (b / BLOCKS_PER_PLANE);
        const int q     = b % BLOCKS_PER_PLANE;
        const int hot   = plane_hot(plane, pose1, pose2);

        float* base = out + (size_t)plane * HW + (size_t)q * QUARTER;
        float4* __restrict__ dst = reinterpret_cast<float4*>(base);
        const float4 z = make_float4(0.0f, 0.0f, 0.0f, 0.0f);
        #pragma unroll
        for (int i = threadIdx.x; i < QUARTER / 4; i += 256) {
            dst[i] = z;
        }

        __syncthreads();
        const int lo = q * QUARTER;
        if (threadIdx.x == 0 && hot >= lo && hot < lo + QUARTER) {
            out[(size_t)plane * HW + hot] = 1.0f;
        }
    } else {
        // ---- head ones: one thread per head plane (memset already zeroed them) ----
        const int plane = (b - FILL_BLOCKS) * 256 + threadIdx.x;
        if (plane < HEAD_PLANES) {
            const int hot = plane_hot(plane, pose1, pose2);
            if (hot >= 0) {
                out[(size_t)plane * HW + hot] = 1.0f;
            }
        }
    }
}

extern "C" void kernel_launch(void* const* d_in, const int* in_sizes, int n_in,
                              void* d_out, int out_size)
{
    const float* pose1 = (const float*)d_in[0];   // [32,18,2] float32
    const float* pose2 = (const float*)d_in[1];   // [32,18,2] float32
    float* out = (float*)d_out;

    (void)in_sizes; (void)n_in; (void)out_size;

    // Zero the head planes via the driver memset path (~7.37 TB/s).
    cudaMemsetAsync(d_out, 0, (size_t)HEAD_PLANES * HW * sizeof(float), 0);

    // Fused: fill+ones for the tail, ones for the head. Stream-ordered after memset.
    cbmodel_fused_tail_kernel<<<GRID, 256>>>(pose1, pose2, out);
}